// round 2
// baseline (speedup 1.0000x reference)
#include <cuda_runtime.h>

#define NB   8      // batches per block
#define TT   512
#define HH   50
#define GG   200    // 4*H
#define NTHR 224    // 7 warps; 200 active in compute phases

typedef unsigned long long u64;

// ---- packed f32x2 helpers (sm_103a FFMA2 path, PTX-only) ----
__device__ __forceinline__ u64 pack2(float x) {
    u64 r; asm("mov.b64 %0, {%1,%1};" : "=l"(r) : "f"(x)); return r;
}
__device__ __forceinline__ u64 fma2(u64 a, u64 b, u64 c) {
    u64 d; asm("fma.rn.f32x2 %0, %1, %2, %3;" : "=l"(d) : "l"(a), "l"(b), "l"(c)); return d;
}

// ---- activations: EX2/RCP based, ~1e-6 accurate ----
__device__ __forceinline__ float sigmoidf_(float x) {
    float e = __expf(-x);
    return __fdividef(1.f, 1.f + e);
}
__device__ __forceinline__ float tanhf_(float x) {
    float ax = fabsf(x);
    float e  = __expf(-2.f * ax);
    float t  = __fdividef(1.f - e, 1.f + e);
    return copysignf(t, x);
}

__global__ void __launch_bounds__(NTHR, 2)
lstm_fused(const float* __restrict__ x,    const float* __restrict__ W_ih,
           const float* __restrict__ W_hh, const float* __restrict__ b_ih,
           const float* __restrict__ b_hh, const float* __restrict__ fc_w,
           const float* __restrict__ fc_b, float* __restrict__ out)
{
    __shared__ __align__(16) float x_sh[TT][NB];   // 16 KB, x transposed [t][b]
    __shared__ __align__(16) float h_sh[HH][NB];   // hidden state, [k][b]
    __shared__ __align__(16) float g_sh[GG][12];   // gate preacts, padded rows (48B)

    const int tid = threadIdx.x;
    const int b0  = blockIdx.x * NB;

    // ---- stage x: global [b][t] (contiguous 16KB) -> shared [t][b] ----
    const float4* xg = reinterpret_cast<const float4*>(x + (size_t)b0 * TT);
    for (int idx = tid; idx < (NB * TT / 4); idx += NTHR) {
        float4 v = xg[idx];
        int e  = idx * 4;
        int bb = e >> 9;          // / 512
        int t  = e & (TT - 1);
        x_sh[t + 0][bb] = v.x; x_sh[t + 1][bb] = v.y;
        x_sh[t + 2][bb] = v.z; x_sh[t + 3][bb] = v.w;
    }
    for (int i = tid; i < HH * NB; i += NTHR) (&h_sh[0][0])[i] = 0.f;

    // ---- per-thread setup: ONE row of W_hh per thread (threads 0..199) ----
    const bool act = (tid < GG);
    float w[HH];
    u64 wx2 = 0, bi2 = 0;
    if (act) {
        #pragma unroll
        for (int k = 0; k < HH; k++) w[k] = W_hh[tid * HH + k];
        wx2 = pack2(W_ih[tid]);
        bi2 = pack2(b_ih[tid] + b_hh[tid]);
    }
    // update-phase mapping: thread tid<200 -> unit uu, batch-pair offset bo
    const int uu = tid >> 2;        // 0..49
    const int bo = (tid & 3) * 2;   // 0,2,4,6
    float c0 = 0.f, c1 = 0.f;

    __syncthreads();

    #pragma unroll 1
    for (int t = 0; t < TT; t++) {
        // ===== gate phase: acc[bpair] = x*wx + bias + sum_k h[bpair][k]*w[k] =====
        if (act) {
            ulonglong2 xp0 = *reinterpret_cast<const ulonglong2*>(&x_sh[t][0]);
            ulonglong2 xp1 = *reinterpret_cast<const ulonglong2*>(&x_sh[t][4]);
            u64 a0 = fma2(xp0.x, wx2, bi2);
            u64 a1 = fma2(xp0.y, wx2, bi2);
            u64 a2 = fma2(xp1.x, wx2, bi2);
            u64 a3 = fma2(xp1.y, wx2, bi2);
            #pragma unroll
            for (int k = 0; k < HH; k++) {
                ulonglong2 hA = *reinterpret_cast<const ulonglong2*>(&h_sh[k][0]);
                ulonglong2 hB = *reinterpret_cast<const ulonglong2*>(&h_sh[k][4]);
                u64 wp = pack2(w[k]);
                a0 = fma2(hA.x, wp, a0);
                a1 = fma2(hA.y, wp, a1);
                a2 = fma2(hB.x, wp, a2);
                a3 = fma2(hB.y, wp, a3);
            }
            ulonglong2 s;
            s.x = a0; s.y = a1; *reinterpret_cast<ulonglong2*>(&g_sh[tid][0]) = s;
            s.x = a2; s.y = a3; *reinterpret_cast<ulonglong2*>(&g_sh[tid][4]) = s;
        }
        __syncthreads();

        // ===== cell update: 2 cells per thread (unit uu, batches bo,bo+1) =====
        if (act) {
            float2 gi = *reinterpret_cast<const float2*>(&g_sh[uu       ][bo]);
            float2 gf = *reinterpret_cast<const float2*>(&g_sh[uu +  50 ][bo]);
            float2 gg = *reinterpret_cast<const float2*>(&g_sh[uu + 100 ][bo]);
            float2 go = *reinterpret_cast<const float2*>(&g_sh[uu + 150 ][bo]);
            c0 = sigmoidf_(gf.x) * c0 + sigmoidf_(gi.x) * tanhf_(gg.x);
            c1 = sigmoidf_(gf.y) * c1 + sigmoidf_(gi.y) * tanhf_(gg.y);
            float2 hn;
            hn.x = sigmoidf_(go.x) * tanhf_(c0);
            hn.y = sigmoidf_(go.y) * tanhf_(c1);
            *reinterpret_cast<float2*>(&h_sh[uu][bo]) = hn;
        }
        __syncthreads();
    }

    // ===== final FC on h_T: out[b][o] = sum_u h[b][u]*fc_w[o][u] + fc_b[o] =====
    if (tid < NB * 3) {
        int bb = tid / 3, o = tid % 3;
        float s = fc_b[o];
        #pragma unroll
        for (int k = 0; k < HH; k++) s += h_sh[k][bb] * fc_w[o * HH + k];
        out[(size_t)(b0 + bb) * 3 + o] = s;
    }
}

extern "C" void kernel_launch(void* const* d_in, const int* in_sizes, int n_in,
                              void* d_out, int out_size) {
    const float* x    = (const float*)d_in[0];
    const float* W_ih = (const float*)d_in[1];
    const float* W_hh = (const float*)d_in[2];
    const float* b_ih = (const float*)d_in[3];
    const float* b_hh = (const float*)d_in[4];
    const float* fc_w = (const float*)d_in[5];
    const float* fc_b = (const float*)d_in[6];
    lstm_fused<<<2048 / NB, NTHR>>>(x, W_ih, W_hh, b_ih, b_hh, fc_w, fc_b, (float*)d_out);
}

// round 3
// speedup vs baseline: 1.3198x; 1.3198x over previous
#include <cuda_runtime.h>

#define NB   8
#define TT   512
#define HH   50
#define NTHR 128

typedef unsigned long long u64;

__device__ __forceinline__ u64 pack2(float x) {
    u64 r; asm("mov.b64 %0, {%1,%1};" : "=l"(r) : "f"(x)); return r;
}
__device__ __forceinline__ u64 fma2(u64 a, u64 b, u64 c) {
    u64 d; asm("fma.rn.f32x2 %0, %1, %2, %3;" : "=l"(d) : "l"(a), "l"(b), "l"(c)); return d;
}
__device__ __forceinline__ void unpk(u64 v, float& lo, float& hi) {
    asm("mov.b64 {%0, %1}, %2;" : "=f"(lo), "=f"(hi) : "l"(v));
}
__device__ __forceinline__ u64 bfly64(u64 v, unsigned m) {
    unsigned lo, hi;
    asm("mov.b64 {%0, %1}, %2;" : "=r"(lo), "=r"(hi) : "l"(v));
    lo = __shfl_xor_sync(m, lo, 1);
    hi = __shfl_xor_sync(m, hi, 1);
    u64 r; asm("mov.b64 %0, {%1, %2};" : "=l"(r) : "r"(lo), "r"(hi));
    return r;
}
__device__ __forceinline__ float tanhap(float x) {
    float y; asm("tanh.approx.f32 %0, %1;" : "=f"(y) : "f"(x)); return y;
}
__device__ __forceinline__ float sigap(float x) {
    return fmaf(tanhap(0.5f * x), 0.5f, 0.5f);
}

__global__ void __launch_bounds__(NTHR, 2)
lstm_fused(const float* __restrict__ x,    const float* __restrict__ W_ih,
           const float* __restrict__ W_hh, const float* __restrict__ b_ih,
           const float* __restrict__ b_hh, const float* __restrict__ fc_w,
           const float* __restrict__ fc_b, float* __restrict__ out)
{
    __shared__ __align__(16) float x_sh[TT][NB];      // 16 KB
    __shared__ __align__(16) float h_sh[2][HH][NB];   // double-buffered hidden

    const int tid = threadIdx.x;
    const int b0  = blockIdx.x * NB;

    // ---- stage x: global [b][t] -> shared [t][b] ----
    const float4* xg = reinterpret_cast<const float4*>(x + (size_t)b0 * TT);
    for (int idx = tid; idx < (NB * TT / 4); idx += NTHR) {
        float4 v = xg[idx];
        int e  = idx * 4;
        int bb = e >> 9;
        int t  = e & (TT - 1);
        x_sh[t + 0][bb] = v.x; x_sh[t + 1][bb] = v.y;
        x_sh[t + 2][bb] = v.z; x_sh[t + 3][bb] = v.w;
    }
    for (int i = tid; i < HH * NB; i += NTHR) (&h_sh[0][0][0])[i] = 0.f;

    // ---- row mapping: even tid=2j -> rows (j: i-gate, j+100: g-gate)
    //                   odd  tid=2j+1 -> rows (j+50: f-gate, j+150: o-gate)
    const bool act = (tid < 2 * HH);
    const int  j   = tid >> 1;
    const int  r0  = (tid & 1) ? (j + HH) : j;
    const int  r1  = r0 + 2 * HH;

    float w0[HH], w1[HH];
    u64 wx0 = 0, wx1 = 0, bi0 = 0, bi1 = 0;
    if (act) {
        #pragma unroll
        for (int k = 0; k < HH; k++) {
            w0[k] = W_hh[r0 * HH + k];
            w1[k] = W_hh[r1 * HH + k];
        }
        wx0 = pack2(W_ih[r0]);
        wx1 = pack2(W_ih[r1]);
        bi0 = pack2(b_ih[r0] + b_hh[r0]);
        bi1 = pack2(b_ih[r1] + b_hh[r1]);
    }
    float c0 = 0.f, c1 = 0.f, c2 = 0.f, c3 = 0.f;

    __syncthreads();

    #pragma unroll 1
    for (int t = 0; t < TT; t++) {
        if (act) {
            const float* hs = &h_sh[t & 1][0][0];
            // ===== gate phase: two rows x 8 batches, accumulators as f32x2 =====
            ulonglong2 xp0 = *reinterpret_cast<const ulonglong2*>(&x_sh[t][0]);
            ulonglong2 xp1 = *reinterpret_cast<const ulonglong2*>(&x_sh[t][4]);
            u64 a00 = fma2(xp0.x, wx0, bi0);
            u64 a01 = fma2(xp0.y, wx0, bi0);
            u64 a02 = fma2(xp1.x, wx0, bi0);
            u64 a03 = fma2(xp1.y, wx0, bi0);
            u64 a10 = fma2(xp0.x, wx1, bi1);
            u64 a11 = fma2(xp0.y, wx1, bi1);
            u64 a12 = fma2(xp1.x, wx1, bi1);
            u64 a13 = fma2(xp1.y, wx1, bi1);
            #pragma unroll
            for (int k = 0; k < HH; k++) {
                ulonglong2 hA = *reinterpret_cast<const ulonglong2*>(hs + k * NB);
                ulonglong2 hB = *reinterpret_cast<const ulonglong2*>(hs + k * NB + 4);
                u64 w0p = pack2(w0[k]);
                u64 w1p = pack2(w1[k]);
                a00 = fma2(hA.x, w0p, a00);
                a01 = fma2(hA.y, w0p, a01);
                a02 = fma2(hB.x, w0p, a02);
                a03 = fma2(hB.y, w0p, a03);
                a10 = fma2(hA.x, w1p, a10);
                a11 = fma2(hA.y, w1p, a11);
                a12 = fma2(hB.x, w1p, a12);
                a13 = fma2(hB.y, w1p, a13);
            }

            // ===== gate exchange via bfly(1): even keeps batches 0-3, odd 4-7
            unsigned m = __activemask();
            u64 s0 = bfly64((tid & 1) ? a00 : a02, m);  // even rx f01 / odd rx i45
            u64 s1 = bfly64((tid & 1) ? a01 : a03, m);  // even rx f23 / odd rx i67
            u64 s2 = bfly64((tid & 1) ? a10 : a12, m);  // even rx o01 / odd rx g45
            u64 s3 = bfly64((tid & 1) ? a11 : a13, m);  // even rx o23 / odd rx g67

            bool ev = !(tid & 1);
            u64 I0 = ev ? a00 : s0,  I1 = ev ? a01 : s1;
            u64 G0 = ev ? a10 : s2,  G1 = ev ? a11 : s3;
            u64 F0 = ev ? s0  : a02, F1 = ev ? s1  : a03;
            u64 O0 = ev ? s2  : a12, O1 = ev ? s3  : a13;

            float i0,i1,i2,i3, f0,f1,f2,f3, g0,g1,g2,g3, o0,o1,o2,o3;
            unpk(I0, i0, i1); unpk(I1, i2, i3);
            unpk(F0, f0, f1); unpk(F1, f2, f3);
            unpk(G0, g0, g1); unpk(G1, g2, g3);
            unpk(O0, o0, o1); unpk(O1, o2, o3);

            // ===== cell update: 4 cells (unit j, batches (tid&1)*4 .. +3) =====
            c0 = sigap(f0) * c0 + sigap(i0) * tanhap(g0);
            c1 = sigap(f1) * c1 + sigap(i1) * tanhap(g1);
            c2 = sigap(f2) * c2 + sigap(i2) * tanhap(g2);
            c3 = sigap(f3) * c3 + sigap(i3) * tanhap(g3);
            float4 hn;
            hn.x = sigap(o0) * tanhap(c0);
            hn.y = sigap(o1) * tanhap(c1);
            hn.z = sigap(o2) * tanhap(c2);
            hn.w = sigap(o3) * tanhap(c3);
            *reinterpret_cast<float4*>(&h_sh[(t + 1) & 1][j][(tid & 1) * 4]) = hn;
        }
        __syncthreads();
    }

    // ===== final FC on h_T (lives in buffer 0 since TT is even) =====
    if (tid < NB * 3) {
        int bb = tid / 3, o = tid % 3;
        float s = fc_b[o];
        #pragma unroll
        for (int k = 0; k < HH; k++) s += h_sh[0][k][bb] * fc_w[o * HH + k];
        out[(size_t)(b0 + bb) * 3 + o] = s;
    }
}

extern "C" void kernel_launch(void* const* d_in, const int* in_sizes, int n_in,
                              void* d_out, int out_size) {
    const float* x    = (const float*)d_in[0];
    const float* W_ih = (const float*)d_in[1];
    const float* W_hh = (const float*)d_in[2];
    const float* b_ih = (const float*)d_in[3];
    const float* b_hh = (const float*)d_in[4];
    const float* fc_w = (const float*)d_in[5];
    const float* fc_b = (const float*)d_in[6];
    lstm_fused<<<2048 / NB, NTHR>>>(x, W_ih, W_hh, b_ih, b_hh, fc_w, fc_b, (float*)d_out);
}

// round 4
// speedup vs baseline: 1.4998x; 1.1364x over previous
#include <cuda_runtime.h>

#define TT   512
#define HH   50
#define NTHR 128

typedef unsigned long long u64;

__device__ __forceinline__ u64 pack2(float x) {
    u64 r; asm("mov.b64 %0, {%1,%1};" : "=l"(r) : "f"(x)); return r;
}
__device__ __forceinline__ u64 fma2(u64 a, u64 b, u64 c) {
    u64 d; asm("fma.rn.f32x2 %0, %1, %2, %3;" : "=l"(d) : "l"(a), "l"(b), "l"(c)); return d;
}
__device__ __forceinline__ void unpk(u64 v, float& lo, float& hi) {
    asm("mov.b64 {%0, %1}, %2;" : "=f"(lo), "=f"(hi) : "l"(v));
}
__device__ __forceinline__ u64 bfly64(u64 v, unsigned m) {
    unsigned lo, hi;
    asm("mov.b64 {%0, %1}, %2;" : "=r"(lo), "=r"(hi) : "l"(v));
    lo = __shfl_xor_sync(m, lo, 1);
    hi = __shfl_xor_sync(m, hi, 1);
    u64 r; asm("mov.b64 %0, {%1, %2};" : "=l"(r) : "r"(lo), "r"(hi));
    return r;
}
__device__ __forceinline__ float tanhap(float x) {
    float y; asm("tanh.approx.f32 %0, %1;" : "=f"(y) : "f"(x)); return y;
}
__device__ __forceinline__ float sigap(float x) {
    return fmaf(tanhap(0.5f * x), 0.5f, 0.5f);
}

// NP = number of batch-pairs (f32x2 accumulators per gate row); NB = 2*NP batches
template<int NP>
__device__ __forceinline__ void run_lstm(
    float (*x_sh)[8], float (*h_sh)[HH][8], int b0, int tid,
    const float* __restrict__ x,    const float* __restrict__ W_ih,
    const float* __restrict__ W_hh, const float* __restrict__ b_ih,
    const float* __restrict__ b_hh, const float* __restrict__ fc_w,
    const float* __restrict__ fc_b, float* __restrict__ out)
{
    constexpr int NB = 2 * NP;

    // ---- stage x: global [b][t] -> shared [t][b] (128 float4 per batch) ----
    const float4* xg = reinterpret_cast<const float4*>(x);
    for (int idx = tid; idx < NB * 128; idx += NTHR) {
        int bb = idx >> 7, t4 = idx & 127;
        float4 v = xg[(size_t)(b0 + bb) * 128 + t4];
        int t = t4 * 4;
        x_sh[t + 0][bb] = v.x; x_sh[t + 1][bb] = v.y;
        x_sh[t + 2][bb] = v.z; x_sh[t + 3][bb] = v.w;
    }
    for (int i = tid; i < HH * 8; i += NTHR) (&h_sh[0][0][0])[i] = 0.f;

    // ---- row mapping: even tid=2j -> rows (j: i-gate, j+100: g-gate)
    //                   odd  tid=2j+1 -> rows (j+50: f-gate, j+150: o-gate)
    const bool act = (tid < 2 * HH);
    const int  j   = tid >> 1;
    const int  r0  = (tid & 1) ? (j + HH) : j;
    const int  r1  = r0 + 2 * HH;

    float w0[HH], w1[HH];
    u64 wx0 = 0, wx1 = 0, bi0 = 0, bi1 = 0;
    if (act) {
        #pragma unroll
        for (int k = 0; k < HH; k++) {
            w0[k] = W_hh[r0 * HH + k];
            w1[k] = W_hh[r1 * HH + k];
        }
        wx0 = pack2(W_ih[r0]);
        wx1 = pack2(W_ih[r1]);
        bi0 = pack2(b_ih[r0] + b_hh[r0]);
        bi1 = pack2(b_ih[r1] + b_hh[r1]);
    }
    float c0 = 0.f, c1 = 0.f, c2 = 0.f, c3 = 0.f;

    __syncthreads();

    #pragma unroll 1
    for (int t = 0; t < TT; t++) {
        if (act) {
            const float* hs = &h_sh[t & 1][0][0];
            // ===== gate phase =====
            u64 xv[NP > 3 ? 4 : 3];
            {
                ulonglong2 q = *reinterpret_cast<const ulonglong2*>(&x_sh[t][0]);
                xv[0] = q.x; xv[1] = q.y;
                if (NP == 4) {
                    ulonglong2 q1 = *reinterpret_cast<const ulonglong2*>(&x_sh[t][4]);
                    xv[2] = q1.x; xv[3] = q1.y;
                } else {
                    xv[2] = *reinterpret_cast<const u64*>(&x_sh[t][4]);
                }
            }
            u64 A0[NP], A1[NP];
            #pragma unroll
            for (int p = 0; p < NP; p++) {
                A0[p] = fma2(xv[p], wx0, bi0);
                A1[p] = fma2(xv[p], wx1, bi1);
            }
            #pragma unroll
            for (int k = 0; k < HH; k++) {
                u64 hv[NP > 3 ? 4 : 3];
                ulonglong2 q = *reinterpret_cast<const ulonglong2*>(hs + k * 8);
                hv[0] = q.x; hv[1] = q.y;
                if (NP == 4) {
                    ulonglong2 q1 = *reinterpret_cast<const ulonglong2*>(hs + k * 8 + 4);
                    hv[2] = q1.x; hv[3] = q1.y;
                } else {
                    hv[2] = *reinterpret_cast<const u64*>(hs + k * 8 + 4);
                }
                u64 w0p = pack2(w0[k]);
                u64 w1p = pack2(w1[k]);
                #pragma unroll
                for (int p = 0; p < NP; p++) {
                    A0[p] = fma2(hv[p], w0p, A0[p]);
                    A1[p] = fma2(hv[p], w1p, A1[p]);
                }
            }

            // ===== gate exchange via bfly(1) =====
            unsigned m = __activemask();
            bool ev = !(tid & 1);
            u64 s0 = bfly64(ev ? A0[2]      : A0[0], m);
            u64 s1 = bfly64(ev ? A1[2]      : A1[0], m);
            u64 s2 = bfly64(ev ? A0[NP - 1] : A0[1], m);
            u64 s3 = bfly64(ev ? A1[NP - 1] : A1[1], m);

            u64 I0 = ev ? A0[0] : s0,      I1 = ev ? A0[1] : s2;
            u64 G0 = ev ? A1[0] : s1,      G1 = ev ? A1[1] : s3;
            u64 F0 = ev ? s0 : A0[2],      F1 = ev ? s2 : A0[NP - 1];
            u64 O0 = ev ? s1 : A1[2],      O1 = ev ? s3 : A1[NP - 1];

            float i0,i1,i2,i3, f0,f1,f2,f3, g0,g1,g2,g3, o0,o1,o2,o3;
            unpk(I0, i0, i1); unpk(I1, i2, i3);
            unpk(F0, f0, f1); unpk(F1, f2, f3);
            unpk(G0, g0, g1); unpk(G1, g2, g3);
            unpk(O0, o0, o1); unpk(O1, o2, o3);

            // ===== cell update (uniform code; odd-lane extras are garbage
            //       for NP==3 and never stored; values stay bounded) =====
            c0 = sigap(f0) * c0 + sigap(i0) * tanhap(g0);
            c1 = sigap(f1) * c1 + sigap(i1) * tanhap(g1);
            c2 = sigap(f2) * c2 + sigap(i2) * tanhap(g2);
            c3 = sigap(f3) * c3 + sigap(i3) * tanhap(g3);
            float4 hn;
            hn.x = sigap(o0) * tanhap(c0);
            hn.y = sigap(o1) * tanhap(c1);
            hn.z = sigap(o2) * tanhap(c2);
            hn.w = sigap(o3) * tanhap(c3);
            float* hw = &h_sh[(t + 1) & 1][j][0];
            if (ev) {
                *reinterpret_cast<float4*>(hw) = hn;
            } else if (NP == 4) {
                *reinterpret_cast<float4*>(hw + 4) = hn;
            } else {
                *reinterpret_cast<float2*>(hw + 4) = make_float2(hn.x, hn.y);
            }
        }
        __syncthreads();
    }

    // ===== final FC on h_T (buffer 0 since TT is even) =====
    if (tid < NB * 3) {
        int bb = tid / 3, o = tid % 3;
        float s = fc_b[o];
        #pragma unroll
        for (int k = 0; k < HH; k++) s += h_sh[0][k][bb] * fc_w[o * HH + k];
        out[(size_t)(b0 + bb) * 3 + o] = s;
    }
}

__global__ void __launch_bounds__(NTHR, 2)
lstm_fused(const float* __restrict__ x,    const float* __restrict__ W_ih,
           const float* __restrict__ W_hh, const float* __restrict__ b_ih,
           const float* __restrict__ b_hh, const float* __restrict__ fc_w,
           const float* __restrict__ fc_b, float* __restrict__ out)
{
    __shared__ __align__(16) float x_sh[TT][8];
    __shared__ __align__(16) float h_sh[2][HH][8];
    const int bid = blockIdx.x;
    // LUT_classic[bid % 148]: bid and bid+148 share an SM. Pair one 8-batch
    // block with one 6-batch block per SM -> even per-SM load (14 batches).
    if (bid < 148) {
        run_lstm<4>(x_sh, h_sh, bid * 8, threadIdx.x,
                    x, W_ih, W_hh, b_ih, b_hh, fc_w, fc_b, out);
    } else {
        run_lstm<3>(x_sh, h_sh, 1184 + (bid - 148) * 6, threadIdx.x,
                    x, W_ih, W_hh, b_ih, b_hh, fc_w, fc_b, out);
    }
}

extern "C" void kernel_launch(void* const* d_in, const int* in_sizes, int n_in,
                              void* d_out, int out_size) {
    const float* x    = (const float*)d_in[0];
    const float* W_ih = (const float*)d_in[1];
    const float* W_hh = (const float*)d_in[2];
    const float* b_ih = (const float*)d_in[3];
    const float* b_hh = (const float*)d_in[4];
    const float* fc_w = (const float*)d_in[5];
    const float* fc_b = (const float*)d_in[6];
    lstm_fused<<<292, NTHR>>>(x, W_ih, W_hh, b_ih, b_hh, fc_w, fc_b, (float*)d_out);
}